// round 9
// baseline (speedup 1.0000x reference)
#include <cuda_runtime.h>
#include <math.h>
#include <stdint.h>

#define T  2048
#define H  2048
#define NH 16
#define HD 128
#define NE 16
#define II 2048
#define I2 4096
#define EPS 1e-6f

// NT kernel: CTA tile 128x256, warp tile 64x64, TBK=32, 8 warps
#define TBM 128
#define TBN 256
#define KBLK_STR 33
#define MBLK_STR 133
#define ASZ 4256                 // A floats per 32-k stage (128 rows)
#define BSZ 8512                 // B floats per 32-k stage (256 rows)
#define GSMEM_NT ((2 * ASZ + 2 * BSZ) * 4)   // 102144 B

// NN kernel (PV): old proven config 128x128, TBK=64
#define APH 4256
#define ATILE64 (2 * APH)
#define GSMEM_NN (4 * ATILE64 * 4)           // 136192 B

// ---------------- scratch ----------------
__device__ float g_h[(size_t)T * H];
__device__ float g_qkv[(size_t)T * 3 * H];
__device__ float g_S[(size_t)NH * T * T];
__device__ float g_attn[(size_t)T * H];
__device__ float g_x2[(size_t)T * H];
__device__ float g_h2[(size_t)T * H];
__device__ float g_logits[(size_t)T * NE];
__device__ float g_topw[T];
__device__ int   g_topi[T];
__device__ int   g_counts[NE];
__device__ int   g_rows[(size_t)NE * T];
__device__ float g_gu[(size_t)T * I2];
__device__ float g_act[(size_t)T * II];
__device__ float g_moe[(size_t)T * H];
__device__ float g_sgu[(size_t)T * I2];
__device__ float g_sact[(size_t)T * II];
__device__ float g_cos[(size_t)T * (HD / 2)];
__device__ float g_sin[(size_t)T * (HD / 2)];

// ---------------- helpers ----------------
__device__ __forceinline__ uint32_t f2tf(float x) {
    uint32_t u;
    asm("cvt.rna.tf32.f32 %0, %1;" : "=r"(u) : "f"(x));
    return u;
}

__device__ __forceinline__ void mma_tf32(float c[4], uint4 a, uint2 b) {
    asm volatile("mma.sync.aligned.m16n8k8.row.col.f32.tf32.tf32.f32 "
                 "{%0,%1,%2,%3}, {%4,%5,%6,%7}, {%8,%9}, {%0,%1,%2,%3};"
                 : "+f"(c[0]), "+f"(c[1]), "+f"(c[2]), "+f"(c[3])
                 : "r"(a.x), "r"(a.y), "r"(a.z), "r"(a.w), "r"(b.x), "r"(b.y));
}

__device__ __forceinline__ float blk_sum(float v) {
    __shared__ float sh[33];
    __syncthreads();
    int lane = threadIdx.x & 31, w = threadIdx.x >> 5;
#pragma unroll
    for (int o = 16; o; o >>= 1) v += __shfl_xor_sync(0xffffffffu, v, o);
    if (lane == 0) sh[w] = v;
    __syncthreads();
    if (threadIdx.x < 32) {
        int nw = (blockDim.x + 31) >> 5;
        float r = (threadIdx.x < nw) ? sh[threadIdx.x] : 0.f;
#pragma unroll
        for (int o = 16; o; o >>= 1) r += __shfl_xor_sync(0xffffffffu, r, o);
        if (threadIdx.x == 0) sh[32] = r;
    }
    __syncthreads();
    return sh[32];
}

__device__ __forceinline__ float blk_max(float v) {
    __shared__ float sh[33];
    __syncthreads();
    int lane = threadIdx.x & 31, w = threadIdx.x >> 5;
#pragma unroll
    for (int o = 16; o; o >>= 1) v = fmaxf(v, __shfl_xor_sync(0xffffffffu, v, o));
    if (lane == 0) sh[w] = v;
    __syncthreads();
    if (threadIdx.x < 32) {
        int nw = (blockDim.x + 31) >> 5;
        float r = (threadIdx.x < nw) ? sh[threadIdx.x] : -3.4e38f;
#pragma unroll
        for (int o = 16; o; o >>= 1) r = fmaxf(r, __shfl_xor_sync(0xffffffffu, r, o));
        if (threadIdx.x == 0) sh[32] = r;
    }
    __syncthreads();
    return sh[32];
}

// permuted layout within one 32-k stage (k0 in [0,32))
__device__ __forceinline__ int a_perm_base(int r, int k0) {
    int mblk = r >> 4, g = r & 7, half = (r >> 3) & 1;
    int kblk = k0 >> 3, k4 = (k0 >> 2) & 1;
    return (mblk * MBLK_STR + kblk * KBLK_STR + g * 4) * 4 + (half + 2 * k4);
}
__device__ __forceinline__ int b_perm_base(int r, int k0) {
    int nblk = r >> 3, g = r & 7;
    int kblk = k0 >> 3, k4 = (k0 >> 2) & 1;
    return (nblk * MBLK_STR + kblk * KBLK_STR + g * 4) * 2 + k4;
}
__device__ __forceinline__ void a_store4(float* As, int base, float4 v) {
    As[base]      = __uint_as_float(f2tf(v.x));
    As[base + 4]  = __uint_as_float(f2tf(v.y));
    As[base + 8]  = __uint_as_float(f2tf(v.z));
    As[base + 12] = __uint_as_float(f2tf(v.w));
}
__device__ __forceinline__ void b_store4(float* Bs, int base, float4 v) {
    Bs[base]     = __uint_as_float(f2tf(v.x));
    Bs[base + 2] = __uint_as_float(f2tf(v.y));
    Bs[base + 4] = __uint_as_float(f2tf(v.z));
    Bs[base + 6] = __uint_as_float(f2tf(v.w));
}

// ---------------- tf32 GEMM NT: 128x256 CTA, 64x64 warp tiles, TBK=32 ----------------
__global__ void __launch_bounds__(256) mma_nt(
    const float* __restrict__ A, int lda, long long sA,
    const float* __restrict__ B, int ldb, long long sB,
    float* __restrict__ C, int ldc, long long sC,
    int M, int N, int K,
    const int* __restrict__ rowsAll, const int* __restrict__ cntAll,
    int causal,
    const float* __restrict__ addA,
    const float* __restrict__ addS, const float* __restrict__ scaleVec)
{
    extern __shared__ float smem[];
    float* As = smem;              // 2 * ASZ
    float* Bs = smem + 2 * ASZ;    // 2 * BSZ
    __shared__ int rid[TBM];

    int z = blockIdx.z;
    A += (size_t)z * sA; B += (size_t)z * sB; C += (size_t)z * sC;
    const int* rows = rowsAll ? rowsAll + (size_t)z * M : 0;
    int Mv = cntAll ? cntAll[z] : M;
    int m0 = blockIdx.y * TBM;
    if (m0 >= Mv) return;
    int n0 = blockIdx.x * TBN;
    if (causal && n0 > m0) return;

    int tid = threadIdx.x;
    if (tid < TBM) {
        int gm = m0 + tid;
        rid[tid] = rows ? (gm < Mv ? rows[gm] : -1) : gm;
    }
    __syncthreads();

    // A loader: 1024 f4 / 256 thr = 4 each; B loader: 2048 f4 / 256 thr = 8 each
    int larow[4], lacol[4], ra[4], abase[4];
#pragma unroll
    for (int i = 0; i < 4; i++) {
        int idx = tid + i * 256;
        larow[i] = idx >> 3;
        lacol[i] = (idx & 7) * 4;
        ra[i] = rid[larow[i]];
        abase[i] = a_perm_base(larow[i], lacol[i]);
    }
    int bbase[8];
#pragma unroll
    for (int i = 0; i < 8; i++) {
        int idx = tid + i * 256;
        bbase[i] = b_perm_base(idx >> 3, (idx & 7) * 4);
    }

    const float4 z4 = make_float4(0.f, 0.f, 0.f, 0.f);
    // preload stage 0
    {
#pragma unroll
        for (int i = 0; i < 4; i++) {
            float4 av = (ra[i] >= 0) ? *(const float4*)(A + (size_t)ra[i] * lda + lacol[i]) : z4;
            a_store4(As, abase[i], av);
        }
#pragma unroll
        for (int i = 0; i < 8; i++) {
            int idx = tid + i * 256;
            float4 bv = *(const float4*)(B + (size_t)(n0 + (idx >> 3)) * ldb + (idx & 7) * 4);
            b_store4(Bs, bbase[i], bv);
        }
    }
    __syncthreads();

    int lane = tid & 31, wid = tid >> 5;
    int wmblk = (wid & 1) * 4;     // 4 m-blocks of 16 rows
    int wnblk = (wid >> 1) * 8;    // 8 n-blocks of 8 cols
    int g = lane >> 2, cc = lane & 3;
    int fragoff = lane;            // g*4+cc == lane

    float acc[4][8][4];
#pragma unroll
    for (int mi = 0; mi < 4; mi++)
#pragma unroll
        for (int ni = 0; ni < 8; ni++)
#pragma unroll
            for (int j = 0; j < 4; j++) acc[mi][ni][j] = 0.f;

    int nt = K >> 5;
    for (int it = 0; it < nt; it++) {
        int buf = it & 1;
        const float* Ab = As + buf * ASZ;
        const float* Bb = Bs + buf * BSZ;
        float* an = As + (buf ^ 1) * ASZ;
        float* bn = Bs + (buf ^ 1) * BSZ;
        bool has_next = (it + 1) < nt;
        int kt = (it + 1) << 5;

        float4 rA[4], rB1[4];
        if (has_next) {
#pragma unroll
            for (int i = 0; i < 4; i++)
                rA[i] = (ra[i] >= 0) ? *(const float4*)(A + (size_t)ra[i] * lda + kt + lacol[i]) : z4;
#pragma unroll
            for (int i = 0; i < 4; i++) {
                int idx = tid + i * 256;
                rB1[i] = *(const float4*)(B + (size_t)(n0 + (idx >> 3)) * ldb + kt + (idx & 7) * 4);
            }
        }

        // substeps 0-1
#pragma unroll
        for (int kblk = 0; kblk < 2; kblk++) {
            uint4 af[4];
            uint2 bf[8];
#pragma unroll
            for (int mi = 0; mi < 4; mi++)
                af[mi] = *(const uint4*)(Ab + ((wmblk + mi) * MBLK_STR + kblk * KBLK_STR + fragoff) * 4);
#pragma unroll
            for (int ni = 0; ni < 8; ni++)
                bf[ni] = *(const uint2*)(Bb + ((wnblk + ni) * MBLK_STR + kblk * KBLK_STR + fragoff) * 2);
#pragma unroll
            for (int mi = 0; mi < 4; mi++)
#pragma unroll
                for (int ni = 0; ni < 8; ni++)
                    mma_tf32(acc[mi][ni], af[mi], bf[ni]);
        }

        // stage first half of next tile, then issue second B half
        float4 rB2[4];
        if (has_next) {
#pragma unroll
            for (int i = 0; i < 4; i++) a_store4(an, abase[i], rA[i]);
#pragma unroll
            for (int i = 0; i < 4; i++) b_store4(bn, bbase[i], rB1[i]);
#pragma unroll
            for (int i = 0; i < 4; i++) {
                int idx = tid + (i + 4) * 256;
                rB2[i] = *(const float4*)(B + (size_t)(n0 + (idx >> 3)) * ldb + kt + (idx & 7) * 4);
            }
        }

        // substeps 2-3
#pragma unroll
        for (int kblk = 2; kblk < 4; kblk++) {
            uint4 af[4];
            uint2 bf[8];
#pragma unroll
            for (int mi = 0; mi < 4; mi++)
                af[mi] = *(const uint4*)(Ab + ((wmblk + mi) * MBLK_STR + kblk * KBLK_STR + fragoff) * 4);
#pragma unroll
            for (int ni = 0; ni < 8; ni++)
                bf[ni] = *(const uint2*)(Bb + ((wnblk + ni) * MBLK_STR + kblk * KBLK_STR + fragoff) * 2);
#pragma unroll
            for (int mi = 0; mi < 4; mi++)
#pragma unroll
                for (int ni = 0; ni < 8; ni++)
                    mma_tf32(acc[mi][ni], af[mi], bf[ni]);
        }

        if (has_next) {
#pragma unroll
            for (int i = 0; i < 4; i++) b_store4(bn, bbase[i + 4], rB2[i]);
            __syncthreads();
        }
    }

    // epilogue with fused residual / scaled add / gather
#pragma unroll
    for (int mi = 0; mi < 4; mi++) {
        int r0 = (wid & 1) * 64 + mi * 16 + g;
        int rr[2] = { rid[r0], rid[r0 + 8] };
#pragma unroll
        for (int half = 0; half < 2; half++) {
            int r = rr[half];
            if (r < 0) continue;
#pragma unroll
            for (int ni = 0; ni < 8; ni++) {
                int col = n0 + (wid >> 1) * 64 + ni * 8 + cc * 2;
                float2 v = make_float2(acc[mi][ni][half * 2], acc[mi][ni][half * 2 + 1]);
                if (addA) {
                    float2 a = *(const float2*)(addA + (size_t)r * ldc + col);
                    v.x += a.x; v.y += a.y;
                }
                if (addS) {
                    float w = scaleVec[r];
                    float2 s = *(const float2*)(addS + (size_t)r * ldc + col);
                    v.x += s.x * w; v.y += s.y * w;
                }
                *(float2*)(C + (size_t)r * ldc + col) = v;
            }
        }
    }
}

// ---------------- tf32 GEMM NN (512 thr), 128x128, TBK=64 (proven R8 version) --------
__device__ __forceinline__ void load_frags_nn(const float* Ab, const float* Bb, int sub,
                                              int wmblk, int wnblk, int fragoff,
                                              uint4 af[2], uint2 bf[4]) {
    int khalf = sub >> 2, kblk = sub & 3;
    const float* Ah = Ab + khalf * APH;
    const float* Bh = Bb + khalf * APH;
#pragma unroll
    for (int mi = 0; mi < 2; mi++)
        af[mi] = *(const uint4*)(Ah + ((wmblk + mi) * MBLK_STR + kblk * KBLK_STR + fragoff) * 4);
#pragma unroll
    for (int ni = 0; ni < 4; ni++)
        bf[ni] = *(const uint2*)(Bh + ((wnblk + ni) * MBLK_STR + kblk * KBLK_STR + fragoff) * 2);
}

__global__ void __launch_bounds__(512) mma_nn(
    const float* __restrict__ A, int lda, long long sA,
    const float* __restrict__ B, int ldb, long long sB,
    float* __restrict__ C, int ldc, long long sC,
    int M, int N, int K, int kcap)
{
    extern __shared__ float smem[];
    float* As = smem;
    float* Bs = smem + 2 * ATILE64;

    int z = blockIdx.z;
    A += (size_t)z * sA; B += (size_t)z * sB; C += (size_t)z * sC;
    int m0 = blockIdx.y * 128;
    int n0 = blockIdx.x * 128;
    int Keff = kcap ? min(K, m0 + 128) : K;

    int tid = threadIdx.x;
    int larow[4], lacol[4], abase[4];
    int lbkr[4], lbng[4], bbase[4];
#pragma unroll
    for (int i = 0; i < 4; i++) {
        int idx = tid + i * 512;
        larow[i] = idx >> 4;
        lacol[i] = (idx & 15) * 4;
        int khalfA = lacol[i] >> 5, k0A = lacol[i] & 31;
        abase[i] = khalfA * APH + a_perm_base(larow[i], k0A);
        lbkr[i] = idx >> 5;
        lbng[i] = (idx & 31) * 4;
        int khalfB = lbkr[i] >> 5, kr = lbkr[i] & 31;
        int kblk = kr >> 3, ccB = kr & 3, k4 = (kr >> 2) & 1;
        int nblk = lbng[i] >> 3, g0 = lbng[i] & 7;
        bbase[i] = khalfB * APH + (nblk * MBLK_STR + kblk * KBLK_STR + g0 * 4 + ccB) * 2 + k4;
    }

    float4 rA[4], rB[4];
#pragma unroll
    for (int i = 0; i < 4; i++) {
        rA[i] = *(const float4*)(A + (size_t)(m0 + larow[i]) * lda + lacol[i]);
        rB[i] = *(const float4*)(B + (size_t)lbkr[i] * ldb + n0 + lbng[i]);
    }
#pragma unroll
    for (int i = 0; i < 4; i++) {
        a_store4(As, abase[i], rA[i]);
        Bs[bbase[i]]      = __uint_as_float(f2tf(rB[i].x));
        Bs[bbase[i] + 8]  = __uint_as_float(f2tf(rB[i].y));
        Bs[bbase[i] + 16] = __uint_as_float(f2tf(rB[i].z));
        Bs[bbase[i] + 24] = __uint_as_float(f2tf(rB[i].w));
    }
    __syncthreads();

    int lane = tid & 31, wid = tid >> 5;
    int wmblk = (wid & 3) * 2, wnblk = (wid >> 2) * 4;
    int g = lane >> 2, cc = lane & 3;
    int fragoff = g * 4 + cc;

    float acc[2][4][4];
#pragma unroll
    for (int mi = 0; mi < 2; mi++)
#pragma unroll
        for (int ni = 0; ni < 4; ni++)
#pragma unroll
            for (int j = 0; j < 4; j++) acc[mi][ni][j] = 0.f;

    uint4 afb[2][2];
    uint2 bfb[2][4];
    int nt = Keff >> 6;
    for (int it = 0; it < nt; it++) {
        int buf = it & 1;
        const float* Ab = As + buf * ATILE64;
        const float* Bb = Bs + buf * ATILE64;
        load_frags_nn(Ab, Bb, 0, wmblk, wnblk, fragoff, afb[0], bfb[0]);
        bool has_next = (it + 1) < nt;
        if (has_next) {
            int kt = (it + 1) << 6;
#pragma unroll
            for (int i = 0; i < 4; i++) {
                rA[i] = *(const float4*)(A + (size_t)(m0 + larow[i]) * lda + kt + lacol[i]);
                rB[i] = *(const float4*)(B + (size_t)(kt + lbkr[i]) * ldb + n0 + lbng[i]);
            }
        }
#pragma unroll
        for (int s = 0; s < 8; s++) {
            int cur = s & 1;
            if (s < 7)
                load_frags_nn(Ab, Bb, s + 1, wmblk, wnblk, fragoff, afb[cur ^ 1], bfb[cur ^ 1]);
#pragma unroll
            for (int mi = 0; mi < 2; mi++)
#pragma unroll
                for (int ni = 0; ni < 4; ni++)
                    mma_tf32(acc[mi][ni], afb[cur][mi], bfb[cur][ni]);
        }
        if (has_next) {
            float* an = As + (buf ^ 1) * ATILE64;
            float* bn = Bs + (buf ^ 1) * ATILE64;
#pragma unroll
            for (int i = 0; i < 4; i++) {
                a_store4(an, abase[i], rA[i]);
                bn[bbase[i]]      = __uint_as_float(f2tf(rB[i].x));
                bn[bbase[i] + 8]  = __uint_as_float(f2tf(rB[i].y));
                bn[bbase[i] + 16] = __uint_as_float(f2tf(rB[i].z));
                bn[bbase[i] + 24] = __uint_as_float(f2tf(rB[i].w));
            }
            __syncthreads();
        }
    }

#pragma unroll
    for (int mi = 0; mi < 2; mi++) {
        int r = m0 + (wid & 3) * 32 + mi * 16 + g;
#pragma unroll
        for (int ni = 0; ni < 4; ni++) {
            int col = n0 + (wid >> 2) * 32 + ni * 8 + cc * 2;
            *(float2*)(C + (size_t)r * ldc + col) = make_float2(acc[mi][ni][0], acc[mi][ni][1]);
            *(float2*)(C + (size_t)(r + 8) * ldc + col) = make_float2(acc[mi][ni][2], acc[mi][ni][3]);
        }
    }
}

// ---------------- rope table (double precision) ----------------
__global__ void rope_table(float* __restrict__ ctab, float* __restrict__ stab) {
    int t = blockIdx.x, i = threadIdx.x;
    double invf = pow(10000.0, -2.0 * (double)i / (double)HD);
    double ang = (double)t * invf;
    ctab[t * (HD / 2) + i] = (float)cos(ang);
    stab[t * (HD / 2) + i] = (float)sin(ang);
}

// ---------------- rmsnorm ----------------
__global__ void rmsnorm_kernel(const float* __restrict__ x, const float* __restrict__ w,
                               float* __restrict__ out, int ncols) {
    int row = blockIdx.x;
    const float* xr = x + (size_t)row * ncols;
    float ss = 0.f;
    for (int i = threadIdx.x; i < ncols; i += blockDim.x) {
        float v = xr[i];
        ss += v * v;
    }
    float tot = blk_sum(ss);
    float inv = rsqrtf(tot / (float)ncols + EPS);
    float* orow = out + (size_t)row * ncols;
    for (int i = threadIdx.x; i < ncols; i += blockDim.x)
        orow[i] = xr[i] * inv * w[i];
}

// ---------------- per-head q/k rmsnorm + rope (table lookup) ----------------
__global__ void qk_norm_rope(float* __restrict__ qkv,
                             const float* __restrict__ qw, const float* __restrict__ kw,
                             const float* __restrict__ ctab, const float* __restrict__ stab) {
    int t = blockIdx.x, h = blockIdx.y, which = blockIdx.z;
    float* base = qkv + (size_t)t * (3 * H) + (size_t)which * H + (size_t)h * HD;
    int d = threadIdx.x;
    float v = base[d];
    float tot = blk_sum(v * v);
    float inv = rsqrtf(tot / (float)HD + EPS);
    const float* w = which ? kw : qw;
    float nv = v * inv * w[d];
    __shared__ float buf[HD];
    buf[d] = nv;
    __syncthreads();
    if (d < HD / 2) {
        int i = d;
        float c = ctab[t * (HD / 2) + i];
        float s = stab[t * (HD / 2) + i];
        float t1 = buf[2 * i], t2 = buf[2 * i + 1];
        base[2 * i]     = t1 * c - t2 * s;
        base[2 * i + 1] = t1 * s + t2 * c;
    }
}

// ---------------- causal softmax ----------------
__global__ void softmax_causal(float* __restrict__ S) {
    int t = blockIdx.x, h = blockIdx.y;
    float* row = S + ((size_t)h * T + t) * T;
    int n = t + 1;
    int fill_end = min(T, ((t >> 7) + 1) << 7);
    const float scale = 0.08838834764831845f;
    float mx = -3.4e38f;
    for (int j = threadIdx.x; j < n; j += blockDim.x)
        mx = fmaxf(mx, row[j] * scale);
    mx = blk_max(mx);
    float sum = 0.f;
    for (int j = threadIdx.x; j < n; j += blockDim.x) {
        float e = expf(row[j] * scale - mx);
        row[j] = e;
        sum += e;
    }
    sum = blk_sum(sum);
    float invs = 1.f / sum;
    for (int j = threadIdx.x; j < n; j += blockDim.x) row[j] *= invs;
    for (int j = n + (int)threadIdx.x; j < fill_end; j += blockDim.x) row[j] = 0.f;
}

// ---------------- elementwise ----------------
__global__ void silu_mul(const float* __restrict__ gu, float* __restrict__ act) {
    int idx = blockIdx.x * blockDim.x + threadIdx.x;
    if (idx >= T * II) return;
    int t = idx / II, i = idx % II;
    float g = gu[(size_t)t * I2 + i];
    float u = gu[(size_t)t * I2 + II + i];
    act[(size_t)t * II + i] = (g / (1.f + expf(-g))) * u;
}

// ---------------- routing ----------------
__global__ void gate_logits(const float* __restrict__ h2, const float* __restrict__ gw,
                            float* __restrict__ logits) {
    int t = blockIdx.x;
    __shared__ float xs[H];
    for (int i = threadIdx.x; i < H; i += blockDim.x) xs[i] = h2[(size_t)t * H + i];
    __syncthreads();
    int warp = threadIdx.x >> 5, lane = threadIdx.x & 31;
    for (int e = warp; e < NE; e += (blockDim.x >> 5)) {
        const float* w = gw + (size_t)e * H;
        float s = 0.f;
        for (int k = lane; k < H; k += 32) s += xs[k] * w[k];
#pragma unroll
        for (int o = 16; o; o >>= 1) s += __shfl_xor_sync(0xffffffffu, s, o);
        if (lane == 0) logits[(size_t)t * NE + e] = s;
    }
}

__global__ void route_topk(const float* __restrict__ logits, float* __restrict__ topw,
                           int* __restrict__ topi) {
    int t = blockIdx.x * blockDim.x + threadIdx.x;
    if (t >= T) return;
    float mx = -3.4e38f;
    int mi = 0;
#pragma unroll
    for (int e = 0; e < NE; e++) {
        float l = logits[(size_t)t * NE + e];
        if (l > mx) { mx = l; mi = e; }
    }
    float s = 0.f;
#pragma unroll
    for (int e = 0; e < NE; e++) s += expf(logits[(size_t)t * NE + e] - mx);
    topw[t] = 1.f / s;
    topi[t] = mi;
}

__global__ void zero_counts(int* c) {
    if (threadIdx.x < NE) c[threadIdx.x] = 0;
}

__global__ void build_route(const int* __restrict__ topi, int* __restrict__ counts,
                            int* __restrict__ rows) {
    int t = blockIdx.x * blockDim.x + threadIdx.x;
    if (t >= T) return;
    int e = topi[t];
    int p = atomicAdd(&counts[e], 1);
    rows[(size_t)e * T + p] = t;
}

// ---------------- host ----------------
#define SYM(p, s) do { void* _v; cudaGetSymbolAddress(&_v, s); p = (decltype(p))_v; } while (0)

extern "C" void kernel_launch(void* const* d_in, const int* in_sizes, int n_in,
                              void* d_out, int out_size) {
    const float* x      = (const float*)d_in[0];
    const float* ln1    = (const float*)d_in[1];
    const float* qkv_w  = (const float*)d_in[2];
    const float* qlnw   = (const float*)d_in[3];
    const float* klnw   = (const float*)d_in[4];
    const float* o_w    = (const float*)d_in[5];
    const float* ln2    = (const float*)d_in[6];
    const float* gate_w = (const float*)d_in[7];
    const float* egu    = (const float*)d_in[8];
    const float* edown  = (const float*)d_in[9];
    const float* sguw   = (const float*)d_in[10];
    const float* sdw    = (const float*)d_in[11];
    float* out = (float*)d_out;

    float *h, *qkv, *S, *attn, *x2, *h2, *logits, *topw, *gu, *act, *moe, *sgu, *sact, *ctab, *stab;
    int *topi, *counts, *rows;
    SYM(h, g_h); SYM(qkv, g_qkv); SYM(S, g_S); SYM(attn, g_attn);
    SYM(x2, g_x2); SYM(h2, g_h2); SYM(logits, g_logits); SYM(topw, g_topw);
    SYM(gu, g_gu); SYM(act, g_act); SYM(moe, g_moe); SYM(sgu, g_sgu); SYM(sact, g_sact);
    SYM(topi, g_topi); SYM(counts, g_counts); SYM(rows, g_rows);
    SYM(ctab, g_cos); SYM(stab, g_sin);

    cudaFuncSetAttribute(mma_nt, cudaFuncAttributeMaxDynamicSharedMemorySize, GSMEM_NT);
    cudaFuncSetAttribute(mma_nn, cudaFuncAttributeMaxDynamicSharedMemorySize, GSMEM_NN);

    rope_table<<<T, HD / 2>>>(ctab, stab);
    rmsnorm_kernel<<<T, 256>>>(x, ln1, h, H);
    // qkv = h @ qkv_w^T   (N=6144 -> 24 n-tiles)
    mma_nt<<<dim3(3 * H / TBN, T / TBM, 1), 256, GSMEM_NT>>>(h, H, 0, qkv_w, H, 0, qkv, 3 * H, 0,
                                                             T, 3 * H, H, 0, 0, 0, 0, 0, 0);
    qk_norm_rope<<<dim3(T, NH, 2), HD>>>(qkv, qlnw, klnw, ctab, stab);
    // S = Q K^T (causal block skip)
    mma_nt<<<dim3(T / TBN, T / TBM, NH), 256, GSMEM_NT>>>(qkv, 3 * H, HD, qkv + H, 3 * H, HD,
                                                          S, T, (long long)T * T, T, T, HD,
                                                          0, 0, 1, 0, 0, 0);
    softmax_causal<<<dim3(T, NH), 256>>>(S);
    // attn = P V (128-wide NN kernel, K capped at diagonal block)
    mma_nn<<<dim3(HD / 128, T / 128, NH), 512, GSMEM_NN>>>(S, T, (long long)T * T, qkv + 2 * H, 3 * H, HD,
                                                           attn, H, HD, T, HD, T, 1);
    // x2 = x + attn @ o_w^T
    mma_nt<<<dim3(H / TBN, T / TBM, 1), 256, GSMEM_NT>>>(attn, H, 0, o_w, H, 0, x2, H, 0,
                                                         T, H, H, 0, 0, 0, x, 0, 0);
    rmsnorm_kernel<<<T, 256>>>(x2, ln2, h2, H);
    gate_logits<<<T, 256>>>(h2, gate_w, logits);
    route_topk<<<(T + 255) / 256, 256>>>(logits, topw, topi);
    zero_counts<<<1, 32>>>(counts);
    build_route<<<(T + 255) / 256, 256>>>(topi, counts, rows);
    // MoE (top-1, gathered)
    mma_nt<<<dim3(I2 / TBN, T / TBM, NE), 256, GSMEM_NT>>>(h2, H, 0, egu, H, (long long)I2 * H,
                                                           gu, I2, 0, T, I2, H, rows, counts, 0, 0, 0, 0);
    silu_mul<<<(T * II + 255) / 256, 256>>>(gu, act);
    mma_nt<<<dim3(H / TBN, T / TBM, NE), 256, GSMEM_NT>>>(act, II, 0, edown, II, (long long)H * II,
                                                          moe, H, 0, T, H, II, rows, counts, 0, 0, 0, 0);
    // shared FFN
    mma_nt<<<dim3(I2 / TBN, T / TBM, 1), 256, GSMEM_NT>>>(h2, H, 0, sguw, H, 0, sgu, I2, 0,
                                                          T, I2, H, 0, 0, 0, 0, 0, 0);
    silu_mul<<<(T * II + 255) / 256, 256>>>(sgu, sact);
    // out = x2 + topw*moe + sact @ sdw^T
    mma_nt<<<dim3(H / TBN, T / TBM, 1), 256, GSMEM_NT>>>(sact, II, 0, sdw, II, 0, out, H, 0,
                                                         T, H, II, 0, 0, 0, x2, moe, topw);
}